// round 12
// baseline (speedup 1.0000x reference)
#include <cuda_runtime.h>
#include <cstdint>

// Problem constants (fixed by the reference setup_inputs)
#define BB     32
#define NN     4096
#define FDIM   128
#define LDH    200
#define KK     8
#define THREADS      256
#define BLKS_PER_B   8
#define ROWS_PER_BLK 512
#define STAGE_ROWS   32
#define NSTAGE       16     // stages per block (16*32 = 512 rows)
#define NBUF         3
#define STAGE_B1     (STAGE_ROWS * FDIM * 4)   // 16384 B (he only)
#define SMEM_BYTES   (NBUF * STAGE_B1 + 512)   // 49664 B -> 4 blocks/SM

#define CANDS  (BLKS_PER_B * KK)   // 64 candidate keys per batch

#define KEY_MAX 0xFFFFFFFFFFFFFFFFull
#define FULL    0xffffffffu

__device__ unsigned long long g_cand[BB * CANDS];
__device__ int g_counter[BB];   // zero-init; finisher resets to 0 each call

static __device__ __forceinline__ unsigned long long umin64(unsigned long long a,
                                                            unsigned long long b) {
    return a < b ? a : b;
}

// ---------------------------------------------------------------------------
// Fused kernel: he staged via cp.async.bulk ring (48KB -> 4 blocks/SM,
// 32 warps/SM); x read by direct coalesced LDG.128 issued BEFORE the
// mbarrier wait (latency overlapped). 8-lane subgroup scoring, per-warp
// top-8, block merge, fused finisher.
// Keys: (score_bits << 32) | (j-1) -> min-order = (score asc, index asc),
// matching lax.top_k(-score) tie-break semantics.
// ---------------------------------------------------------------------------
__global__ __launch_bounds__(THREADS, 4)
void fused_kernel(const float* __restrict__ x,   // (B, N, FDIM)
                  const float* __restrict__ hf,  // (B, N, L, DH)
                  const float* __restrict__ he,  // (B, N, FDIM)
                  unsigned long long* __restrict__ cand,
                  float* __restrict__ out)
{
    const int b   = blockIdx.x / BLKS_PER_B;
    const int blk = blockIdx.x % BLKS_PER_B;
    const int t   = threadIdx.x;
    const int w   = t >> 5;        // warp 0..7
    const int l   = t & 31;        // lane
    const int sg  = l >> 3;        // subgroup 0..3 (row within warp's 4)
    const int sl  = l & 7;         // slice lane 0..7 (16 floats each)
    const int j0  = 1 + blk * ROWS_PER_BLK;

    extern __shared__ char dynsmem[];
    const uint32_t smem_u32 = (uint32_t)__cvta_generic_to_shared(dynsmem);
    float4* scx = (float4*)(dynsmem + NBUF * STAGE_B1);   // center x row (32 f4)

    __shared__ unsigned long long mbar[NBUF];
    __shared__ unsigned long long skeys[64];
    __shared__ int s_last;
    __shared__ int sel_idx[KK];
    const uint32_t mbar_u32 = (uint32_t)__cvta_generic_to_shared(mbar);

    const float* xrow = x  + (size_t)b * NN * FDIM;
    const float* urow = he + (size_t)b * NN * FDIM;
    const float4* xb4 = (const float4*)xrow;
    const float4* ub4 = (const float4*)urow;

    // stage x center row into smem; init mbarriers
    if (t < 32) scx[t] = xb4[t];
    if (t == 0) {
        #pragma unroll
        for (int s = 0; s < NBUF; s++)
            asm volatile("mbarrier.init.shared.b64 [%0], 1;"
                         :: "r"(mbar_u32 + s * 8) : "memory");
        asm volatile("fence.proxy.async.shared::cta;" ::: "memory");
    }
    __syncthreads();

    // ---- bulk-issue stage cc (he rows) into buffer cc%3 (single thread) ----
    auto issue = [&](int cc) {
        if (t == 0) {
            const int st   = cc % NBUF;
            const int row0 = j0 + cc * STAGE_ROWS;
            int nrows = NN - row0; if (nrows > STAGE_ROWS) nrows = STAGE_ROWS;
            const uint32_t bytes1 = (uint32_t)nrows * (FDIM * 4);
            const uint32_t mb = mbar_u32 + st * 8;
            asm volatile("mbarrier.arrive.expect_tx.shared.b64 _, [%0], %1;"
                         :: "r"(mb), "r"(bytes1) : "memory");
            asm volatile(
                "cp.async.bulk.shared::cta.global.mbarrier::complete_tx::bytes "
                "[%0], [%1], %2, [%3];"
                :: "r"(smem_u32 + (uint32_t)st * STAGE_B1),
                   "l"(urow + (size_t)row0 * FDIM), "r"(bytes1), "r"(mb)
                : "memory");
        }
    };

    auto waitbar = [&](int st, int phase) {
        const uint32_t mb = mbar_u32 + st * 8;
        asm volatile(
            "{\n\t.reg .pred P1;\n"
            "W_%=:\n\t"
            "mbarrier.try_wait.parity.acquire.cta.shared::cta.b64 P1, [%0], %1;\n\t"
            "@P1 bra.uni D_%=;\n\t"
            "bra.uni W_%=;\n"
            "D_%=:\n\t}"
            :: "r"(mb), "r"(phase) : "memory");
    };

    issue(0);
    issue(1);
    issue(2);

    // ---- he center slice in registers + center-embed norm ----
    float4 V[4];
    #pragma unroll
    for (int q = 0; q < 4; q++) V[q] = ub4[q * 8 + sl];

    float vv = 0.0f;
    #pragma unroll
    for (int q = 0; q < 4; q++)
        vv += V[q].x*V[q].x + V[q].y*V[q].y + V[q].z*V[q].z + V[q].w*V[q].w;
    #pragma unroll
    for (int off = 1; off < 8; off <<= 1)
        vv += __shfl_xor_sync(FULL, vv, off);
    const float vnm = fmaxf(sqrtf(vv), 1e-8f);

    // ---- center direction (uniform) ----
    const float* h0 = hf + (size_t)b * NN * LDH;
    float2 p048 = *(const float2*)(h0 + 192);
    float2 p049 = *(const float2*)(h0 + 196);
    float d0x = p049.x - p048.x, d0y = p049.y - p048.y;
    float inv0 = 1.0f / fmaxf(sqrtf(d0x*d0x + d0y*d0y), 1e-12f);
    const float cdx = d0x * inv0 + 1e-8f;
    const float cdy = d0y * inv0 + 1e-8f;
    const float cnorm = fmaxf(sqrtf(cdx*cdx + cdy*cdy), 1e-8f);

    // ---- vsim precompute: lane l holds agents idx=l (lo), idx=l+32 (hi)
    //      row(idx) = j0 + (idx>>2)*32 + w*4 + (idx&3) ----
    auto vsim_of = [&](int row) -> float {
        int r = row < NN ? row : NN - 1;
        const float* hj = hf + ((size_t)b * NN + r) * LDH;
        float2 a48 = *(const float2*)(hj + 192);
        float2 a49 = *(const float2*)(hj + 196);
        float djx = a49.x - a48.x, djy = a49.y - a48.y;
        float invj = 1.0f / fmaxf(sqrtf(djx*djx + djy*djy), 1e-12f);
        float odx = djx * invj + 1e-8f;
        float ody = djy * invj + 1e-8f;
        float vnum = odx*cdx + ody*cdy;
        float vden = fmaxf(sqrtf(odx*odx + ody*ody), 1e-8f) * cnorm;
        return vnum / vden;
    };
    const int row_lo = j0 + (l >> 2) * 32 + w * 4 + (l & 3);
    const float vs_lo = vsim_of(row_lo);
    const float vs_hi = vsim_of(row_lo + 256);

    // ---- main loop: 16 row-stages ----
    unsigned long long k0 = KEY_MAX, k1 = KEY_MAX;

    #pragma unroll 2
    for (int cc = 0; cc < NSTAGE; cc++) {
        // issue this subgroup's x-row LDGs BEFORE the barrier wait so their
        // latency overlaps it (coalesced: 4 rows x one 128B line per instr)
        const int rowg = j0 + cc * STAGE_ROWS + w * 4 + sg;
        const int rs   = rowg < NN ? rowg : NN - 1;
        const float4* xg = xb4 + (size_t)rs * 32;
        float4 A0 = xg[sl];
        float4 A1 = xg[8 + sl];
        float4 A2 = xg[16 + sl];
        float4 A3 = xg[24 + sl];

        waitbar(cc % NBUF, (cc / NBUF) & 1);

        const float4* su = (const float4*)(dynsmem + (cc % NBUF) * STAGE_B1)
                           + (w * 4 + sg) * (FDIM / 4);

        float d2 = 0.0f, tn = 0.0f, uu = 0.0f;
        {
            float4 Cq = scx[sl];
            float ex = A0.x - Cq.x, ey = A0.y - Cq.y, ez = A0.z - Cq.z, ew = A0.w - Cq.w;
            d2 += ex*ex + ey*ey + ez*ez + ew*ew;
            float4 U = su[sl];
            tn += U.x*V[0].x + U.y*V[0].y + U.z*V[0].z + U.w*V[0].w;
            uu += U.x*U.x + U.y*U.y + U.z*U.z + U.w*U.w;
        }
        {
            float4 Cq = scx[8 + sl];
            float ex = A1.x - Cq.x, ey = A1.y - Cq.y, ez = A1.z - Cq.z, ew = A1.w - Cq.w;
            d2 += ex*ex + ey*ey + ez*ez + ew*ew;
            float4 U = su[8 + sl];
            tn += U.x*V[1].x + U.y*V[1].y + U.z*V[1].z + U.w*V[1].w;
            uu += U.x*U.x + U.y*U.y + U.z*U.z + U.w*U.w;
        }
        {
            float4 Cq = scx[16 + sl];
            float ex = A2.x - Cq.x, ey = A2.y - Cq.y, ez = A2.z - Cq.z, ew = A2.w - Cq.w;
            d2 += ex*ex + ey*ey + ez*ez + ew*ew;
            float4 U = su[16 + sl];
            tn += U.x*V[2].x + U.y*V[2].y + U.z*V[2].z + U.w*V[2].w;
            uu += U.x*U.x + U.y*U.y + U.z*U.z + U.w*U.w;
        }
        {
            float4 Cq = scx[24 + sl];
            float ex = A3.x - Cq.x, ey = A3.y - Cq.y, ez = A3.z - Cq.z, ew = A3.w - Cq.w;
            d2 += ex*ex + ey*ey + ez*ez + ew*ew;
            float4 U = su[24 + sl];
            tn += U.x*V[3].x + U.y*V[3].y + U.z*V[3].z + U.w*V[3].w;
            uu += U.x*U.x + U.y*U.y + U.z*U.z + U.w*U.w;
        }

        #pragma unroll
        for (int off = 1; off < 8; off <<= 1) {
            d2 += __shfl_xor_sync(FULL, d2, off);
            tn += __shfl_xor_sync(FULL, tn, off);
            uu += __shfl_xor_sync(FULL, uu, off);
        }

        // vsim for this subgroup's agent: lives on lane ((cc&7)*4 + sg)
        float vsrc = (cc < 8) ? vs_lo : vs_hi;
        float vs = __shfl_sync(FULL, vsrc, ((cc & 7) << 2) + sg);

        float tsim  = tn / (fmaxf(sqrtf(uu), 1e-8f) * vnm);
        float score = 0.3f * sqrtf(d2)
                    + 0.5f * (1.0f - fmaxf(vs,   0.0f))
                    + 0.4f * (1.0f - fmaxf(tsim, 0.0f));
        score = fmaxf(score, 0.0f);   // keep bit-pattern order-preserving

        // collector: lane with (l>>2)==(cc&7) stores subgroup (l&3)'s key
        float sc = __shfl_sync(FULL, score, (l & 3) << 3);
        const int jc = j0 + cc * 32 + w * 4 + (l & 3);
        if ((l >> 2) == (cc & 7) && jc < NN) {
            unsigned long long key =
                ((unsigned long long)__float_as_uint(sc) << 32)
                | (unsigned int)(jc - 1);
            if (cc < 8) k0 = key; else k1 = key;
        }

        __syncthreads();   // buffer cc%3 fully consumed -> safe to refill
        if (cc + 3 < NSTAGE) issue(cc + 3);
    }

    // ---- warp top-8 over 64 keys (2 per lane) ----
    unsigned long long sel = KEY_MAX;
    #pragma unroll
    for (int it = 0; it < KK; it++) {
        unsigned long long m = umin64(k0, k1);
        #pragma unroll
        for (int off = 16; off > 0; off >>= 1)
            m = umin64(m, __shfl_xor_sync(FULL, m, off));
        if (k0 == m) k0 = KEY_MAX;
        else if (k1 == m) k1 = KEY_MAX;
        if (l == it) sel = m;
    }
    if (l < KK) skeys[w * KK + l] = sel;
    __syncthreads();

    // ---- block merge: warp 0 reduces 64 -> 8, writes candidates ----
    if (w == 0) {
        unsigned long long a0 = skeys[l];
        unsigned long long a1 = skeys[l + 32];
        unsigned long long sel2 = KEY_MAX;
        #pragma unroll
        for (int it = 0; it < KK; it++) {
            unsigned long long m = umin64(a0, a1);
            #pragma unroll
            for (int off = 16; off > 0; off >>= 1)
                m = umin64(m, __shfl_xor_sync(FULL, m, off));
            if (a0 == m) a0 = KEY_MAX;
            else if (a1 == m) a1 = KEY_MAX;
            if (l == it) sel2 = m;
        }
        if (l < KK)
            cand[(size_t)b * CANDS + blk * KK + l] = sel2;
    }

    // ---- arrival protocol: last block of this batch merges + gathers ----
    __threadfence();
    __syncthreads();
    if (t == 0) {
        int old = atomicAdd(&g_counter[b], 1);
        s_last = (old == BLKS_PER_B - 1) ? 1 : 0;
    }
    __syncthreads();
    if (!s_last) return;

    __threadfence();   // acquire: see all other blocks' cand writes

    if (t < 32) {
        unsigned long long q0 = cand[(size_t)b * CANDS + t];
        unsigned long long q1 = cand[(size_t)b * CANDS + 32 + t];
        #pragma unroll
        for (int it = 0; it < KK; it++) {
            unsigned long long m = umin64(q0, q1);
            #pragma unroll
            for (int off = 16; off > 0; off >>= 1)
                m = umin64(m, __shfl_xor_sync(FULL, m, off));
            if (q0 == m) q0 = KEY_MAX;
            else if (q1 == m) q1 = KEY_MAX;
            if (t == 0) sel_idx[it] = (int)(unsigned int)(m & 0xFFFFFFFFu);
        }
        if (t == 0) g_counter[b] = 0;   // reset for next graph replay
    }
    __syncthreads();

    // gather: 256 threads = 8 rows x 32 lanes of float4
    {
        const int kk  = t >> 5;
        const int idx = sel_idx[kk];
        float4 val = xb4[(size_t)(idx + 1) * 32 + l];
        ((float4*)(out + ((size_t)b * KK + kk) * FDIM))[l] = val;
    }
    if (t < KK)
        out[(size_t)BB * KK * FDIM + b * KK + t] = (float)sel_idx[t];
}

extern "C" void kernel_launch(void* const* d_in, const int* in_sizes, int n_in,
                              void* d_out, int out_size)
{
    const float* x  = (const float*)d_in[0];   // (B, N, FDIM) f32
    const float* hf = (const float*)d_in[1];   // (B, N, L, DH) f32
    const float* he = (const float*)d_in[2];   // (B, N, FDIM) f32
    float* out = (float*)d_out;

    unsigned long long* cand;
    cudaGetSymbolAddress((void**)&cand, g_cand);

    cudaFuncSetAttribute(fused_kernel,
                         cudaFuncAttributeMaxDynamicSharedMemorySize, SMEM_BYTES);

    fused_kernel<<<BB * BLKS_PER_B, THREADS, SMEM_BYTES>>>(x, hf, he, cand, out);
}

// round 13
// speedup vs baseline: 1.1304x; 1.1304x over previous
#include <cuda_runtime.h>
#include <cstdint>

// Problem constants (fixed by the reference setup_inputs)
#define BB     32
#define NN     4096
#define FDIM   128
#define LDH    200
#define KK     8
#define THREADS      256
#define BLKS_PER_B   8
#define ROWS_PER_BLK 512
#define STAGE_ROWS   32
#define NSTAGE       16     // stages per block (16*32 = 512 rows)
#define NBUF         2
#define STAGE_B1     (STAGE_ROWS * FDIM * 4)   // 16384 B per array
#define STAGE_B      (2 * STAGE_B1)            // 32768 B per stage
#define SMEM_BYTES   (NBUF * STAGE_B)          // 65536 B -> 3 blocks/SM

#define CANDS  (BLKS_PER_B * KK)   // 64 candidate keys per batch

#define KEY_MAX 0xFFFFFFFFFFFFFFFFull
#define FULL    0xffffffffu

__device__ unsigned long long g_cand[BB * CANDS];
__device__ int g_counter[BB];   // zero-init; finisher resets to 0 each call

static __device__ __forceinline__ unsigned long long umin64(unsigned long long a,
                                                            unsigned long long b) {
    return a < b ? a : b;
}

// ---------------------------------------------------------------------------
// Fused kernel: cp.async.bulk row-staged DOUBLE-buffer ring (64KB -> 3
// blocks/SM, 24 warps/SM), 8-lane subgroup scoring from smem, per-warp
// top-8, block merge, fused finisher.
// Keys: (score_bits << 32) | (j-1) -> min-order = (score asc, index asc),
// matching lax.top_k(-score) tie-break semantics.
// ---------------------------------------------------------------------------
__global__ __launch_bounds__(THREADS, 3)
void fused_kernel(const float* __restrict__ x,   // (B, N, FDIM)
                  const float* __restrict__ hf,  // (B, N, L, DH)
                  const float* __restrict__ he,  // (B, N, FDIM)
                  unsigned long long* __restrict__ cand,
                  float* __restrict__ out)
{
    const int b   = blockIdx.x / BLKS_PER_B;
    const int blk = blockIdx.x % BLKS_PER_B;
    const int t   = threadIdx.x;
    const int w   = t >> 5;        // warp 0..7
    const int l   = t & 31;        // lane
    const int sg  = l >> 3;        // subgroup 0..3 (row within warp's 4)
    const int sl  = l & 7;         // slice lane 0..7 (16 floats each)
    const int j0  = 1 + blk * ROWS_PER_BLK;

    extern __shared__ char dynsmem[];
    const uint32_t smem_u32 = (uint32_t)__cvta_generic_to_shared(dynsmem);

    __shared__ unsigned long long mbar[NBUF];
    __shared__ unsigned long long skeys[64];
    __shared__ int s_last;
    __shared__ int sel_idx[KK];
    const uint32_t mbar_u32 = (uint32_t)__cvta_generic_to_shared(mbar);

    if (t == 0) {
        #pragma unroll
        for (int s = 0; s < NBUF; s++)
            asm volatile("mbarrier.init.shared.b64 [%0], 1;"
                         :: "r"(mbar_u32 + s * 8) : "memory");
        asm volatile("fence.proxy.async.shared::cta;" ::: "memory");
    }
    __syncthreads();

    const float* xrow = x  + (size_t)b * NN * FDIM;
    const float* urow = he + (size_t)b * NN * FDIM;
    const float4* xb4 = (const float4*)xrow;
    const float4* ub4 = (const float4*)urow;

    // ---- bulk-issue stage cc into buffer cc%2 (single thread) ----
    auto issue = [&](int cc) {
        if (t == 0) {
            const int st   = cc & 1;
            const int row0 = j0 + cc * STAGE_ROWS;
            int nrows = NN - row0; if (nrows > STAGE_ROWS) nrows = STAGE_ROWS;
            const uint32_t bytes1 = (uint32_t)nrows * (FDIM * 4);
            const uint32_t mb = mbar_u32 + st * 8;
            asm volatile("mbarrier.arrive.expect_tx.shared.b64 _, [%0], %1;"
                         :: "r"(mb), "r"(2u * bytes1) : "memory");
            const uint32_t d0 = smem_u32 + (uint32_t)st * STAGE_B;
            asm volatile(
                "cp.async.bulk.shared::cta.global.mbarrier::complete_tx::bytes "
                "[%0], [%1], %2, [%3];"
                :: "r"(d0), "l"(xrow + (size_t)row0 * FDIM), "r"(bytes1), "r"(mb)
                : "memory");
            asm volatile(
                "cp.async.bulk.shared::cta.global.mbarrier::complete_tx::bytes "
                "[%0], [%1], %2, [%3];"
                :: "r"(d0 + STAGE_B1), "l"(urow + (size_t)row0 * FDIM), "r"(bytes1), "r"(mb)
                : "memory");
        }
    };

    auto waitbar = [&](int st, int phase) {
        const uint32_t mb = mbar_u32 + st * 8;
        asm volatile(
            "{\n\t.reg .pred P1;\n"
            "W_%=:\n\t"
            "mbarrier.try_wait.parity.acquire.cta.shared::cta.b64 P1, [%0], %1;\n\t"
            "@P1 bra.uni D_%=;\n\t"
            "bra.uni W_%=;\n"
            "D_%=:\n\t}"
            :: "r"(mb), "r"(phase) : "memory");
    };

    issue(0);
    issue(1);

    // ---- centers in registers: this lane's 16-float slice (f4s q*8+sl) ----
    float4 C[4], V[4];
    #pragma unroll
    for (int q = 0; q < 4; q++) { C[q] = xb4[q * 8 + sl]; V[q] = ub4[q * 8 + sl]; }

    float vv = 0.0f;
    #pragma unroll
    for (int q = 0; q < 4; q++)
        vv += V[q].x*V[q].x + V[q].y*V[q].y + V[q].z*V[q].z + V[q].w*V[q].w;
    #pragma unroll
    for (int off = 1; off < 8; off <<= 1)
        vv += __shfl_xor_sync(FULL, vv, off);
    const float vnm = fmaxf(sqrtf(vv), 1e-8f);

    // ---- center direction (uniform) ----
    const float* h0 = hf + (size_t)b * NN * LDH;
    float2 p048 = *(const float2*)(h0 + 192);
    float2 p049 = *(const float2*)(h0 + 196);
    float d0x = p049.x - p048.x, d0y = p049.y - p048.y;
    float inv0 = 1.0f / fmaxf(sqrtf(d0x*d0x + d0y*d0y), 1e-12f);
    const float cdx = d0x * inv0 + 1e-8f;
    const float cdy = d0y * inv0 + 1e-8f;
    const float cnorm = fmaxf(sqrtf(cdx*cdx + cdy*cdy), 1e-8f);

    // ---- vsim precompute: lane l holds agents idx=l (lo) and idx=l+32 (hi)
    //      row(idx) = j0 + (idx>>2)*32 + w*4 + (idx&3) ----
    auto vsim_of = [&](int row) -> float {
        int r = row < NN ? row : NN - 1;
        const float* hj = hf + ((size_t)b * NN + r) * LDH;
        float2 a48 = *(const float2*)(hj + 192);
        float2 a49 = *(const float2*)(hj + 196);
        float djx = a49.x - a48.x, djy = a49.y - a48.y;
        float invj = 1.0f / fmaxf(sqrtf(djx*djx + djy*djy), 1e-12f);
        float odx = djx * invj + 1e-8f;
        float ody = djy * invj + 1e-8f;
        float vnum = odx*cdx + ody*cdy;
        float vden = fmaxf(sqrtf(odx*odx + ody*ody), 1e-8f) * cnorm;
        return vnum / vden;
    };
    const int row_lo = j0 + (l >> 2) * 32 + w * 4 + (l & 3);
    const float vs_lo = vsim_of(row_lo);
    const float vs_hi = vsim_of(row_lo + 256);

    // ---- main loop: 16 row-stages ----
    unsigned long long k0 = KEY_MAX, k1 = KEY_MAX;

    #pragma unroll 2
    for (int cc = 0; cc < NSTAGE; cc++) {
        waitbar(cc & 1, (cc >> 1) & 1);

        // this subgroup's row in the staged buffer
        const float4* sx = (const float4*)(dynsmem + (cc & 1) * STAGE_B)
                           + (w * 4 + sg) * (FDIM / 4);
        const float4* su = (const float4*)(dynsmem + (cc & 1) * STAGE_B + STAGE_B1)
                           + (w * 4 + sg) * (FDIM / 4);

        float d2 = 0.0f, tn = 0.0f, uu = 0.0f;
        #pragma unroll
        for (int q = 0; q < 4; q++) {
            float4 A = sx[q * 8 + sl];
            float4 U = su[q * 8 + sl];
            float ex = A.x - C[q].x, ey = A.y - C[q].y,
                  ez = A.z - C[q].z, ew = A.w - C[q].w;
            d2 += ex*ex + ey*ey + ez*ez + ew*ew;
            tn += U.x*V[q].x + U.y*V[q].y + U.z*V[q].z + U.w*V[q].w;
            uu += U.x*U.x + U.y*U.y + U.z*U.z + U.w*U.w;
        }
        #pragma unroll
        for (int off = 1; off < 8; off <<= 1) {
            d2 += __shfl_xor_sync(FULL, d2, off);
            tn += __shfl_xor_sync(FULL, tn, off);
            uu += __shfl_xor_sync(FULL, uu, off);
        }

        // vsim for this subgroup's agent: lives on lane ((cc&7)*4 + sg)
        float vsrc = (cc < 8) ? vs_lo : vs_hi;
        float vs = __shfl_sync(FULL, vsrc, ((cc & 7) << 2) + sg);

        float tsim  = tn / (fmaxf(sqrtf(uu), 1e-8f) * vnm);
        float score = 0.3f * sqrtf(d2)
                    + 0.5f * (1.0f - fmaxf(vs,   0.0f))
                    + 0.4f * (1.0f - fmaxf(tsim, 0.0f));
        score = fmaxf(score, 0.0f);   // keep bit-pattern order-preserving

        // collector: lane with (l>>2)==(cc&7) stores subgroup (l&3)'s key
        float sc = __shfl_sync(FULL, score, (l & 3) << 3);
        const int jc = j0 + cc * 32 + w * 4 + (l & 3);
        if ((l >> 2) == (cc & 7) && jc < NN) {
            unsigned long long key =
                ((unsigned long long)__float_as_uint(sc) << 32)
                | (unsigned int)(jc - 1);
            if (cc < 8) k0 = key; else k1 = key;
        }

        // all warps done reading buffer cc%2 -> safe to refill it (stage cc+2)
        __syncthreads();
        if (cc + 2 < NSTAGE) issue(cc + 2);
    }

    // ---- warp top-8 over 64 keys (2 per lane) ----
    unsigned long long sel = KEY_MAX;
    #pragma unroll
    for (int it = 0; it < KK; it++) {
        unsigned long long m = umin64(k0, k1);
        #pragma unroll
        for (int off = 16; off > 0; off >>= 1)
            m = umin64(m, __shfl_xor_sync(FULL, m, off));
        if (k0 == m) k0 = KEY_MAX;
        else if (k1 == m) k1 = KEY_MAX;
        if (l == it) sel = m;
    }
    if (l < KK) skeys[w * KK + l] = sel;
    __syncthreads();

    // ---- block merge: warp 0 reduces 64 -> 8, writes candidates ----
    if (w == 0) {
        unsigned long long a0 = skeys[l];
        unsigned long long a1 = skeys[l + 32];
        unsigned long long sel2 = KEY_MAX;
        #pragma unroll
        for (int it = 0; it < KK; it++) {
            unsigned long long m = umin64(a0, a1);
            #pragma unroll
            for (int off = 16; off > 0; off >>= 1)
                m = umin64(m, __shfl_xor_sync(FULL, m, off));
            if (a0 == m) a0 = KEY_MAX;
            else if (a1 == m) a1 = KEY_MAX;
            if (l == it) sel2 = m;
        }
        if (l < KK)
            cand[(size_t)b * CANDS + blk * KK + l] = sel2;
    }

    // ---- arrival protocol: last block of this batch merges + gathers ----
    __threadfence();
    __syncthreads();
    if (t == 0) {
        int old = atomicAdd(&g_counter[b], 1);
        s_last = (old == BLKS_PER_B - 1) ? 1 : 0;
    }
    __syncthreads();
    if (!s_last) return;

    __threadfence();   // acquire: see all other blocks' cand writes

    if (t < 32) {
        unsigned long long q0 = cand[(size_t)b * CANDS + t];
        unsigned long long q1 = cand[(size_t)b * CANDS + 32 + t];
        #pragma unroll
        for (int it = 0; it < KK; it++) {
            unsigned long long m = umin64(q0, q1);
            #pragma unroll
            for (int off = 16; off > 0; off >>= 1)
                m = umin64(m, __shfl_xor_sync(FULL, m, off));
            if (q0 == m) q0 = KEY_MAX;
            else if (q1 == m) q1 = KEY_MAX;
            if (t == 0) sel_idx[it] = (int)(unsigned int)(m & 0xFFFFFFFFu);
        }
        if (t == 0) g_counter[b] = 0;   // reset for next graph replay
    }
    __syncthreads();

    // gather: 256 threads = 8 rows x 32 lanes of float4
    {
        const int kk  = t >> 5;
        const int idx = sel_idx[kk];
        float4 val = xb4[(size_t)(idx + 1) * 32 + l];
        ((float4*)(out + ((size_t)b * KK + kk) * FDIM))[l] = val;
    }
    if (t < KK)
        out[(size_t)BB * KK * FDIM + b * KK + t] = (float)sel_idx[t];
}

extern "C" void kernel_launch(void* const* d_in, const int* in_sizes, int n_in,
                              void* d_out, int out_size)
{
    const float* x  = (const float*)d_in[0];   // (B, N, FDIM) f32
    const float* hf = (const float*)d_in[1];   // (B, N, L, DH) f32
    const float* he = (const float*)d_in[2];   // (B, N, FDIM) f32
    float* out = (float*)d_out;

    unsigned long long* cand;
    cudaGetSymbolAddress((void**)&cand, g_cand);

    cudaFuncSetAttribute(fused_kernel,
                         cudaFuncAttributeMaxDynamicSharedMemorySize, SMEM_BYTES);

    fused_kernel<<<BB * BLKS_PER_B, THREADS, SMEM_BYTES>>>(x, hf, he, cand, out);
}

// round 14
// speedup vs baseline: 1.1837x; 1.0471x over previous
#include <cuda_runtime.h>
#include <cstdint>

// Problem constants (fixed by the reference setup_inputs)
#define BB     32
#define NN     4096
#define FDIM   128
#define LDH    200
#define KK     8
#define THREADS      256
#define BLKS_PER_B   8
#define ROWS_PER_BLK 512
#define STAGE_ROWS   32
#define NSTAGE       16     // stages per block (16*32 = 512 rows)
#define NBUF         3
#define STAGE_B1     (STAGE_ROWS * FDIM * 4)   // 16384 B per array
#define STAGE_B      (2 * STAGE_B1)            // 32768 B per stage
#define SMEM_BYTES   (NBUF * STAGE_B)          // 98304 B -> 2 blocks/SM

#define CANDS  (BLKS_PER_B * KK)   // 64 candidate keys per batch

#define KEY_MAX 0xFFFFFFFFFFFFFFFFull
#define FULL    0xffffffffu

__device__ unsigned long long g_cand[BB * CANDS];
__device__ int g_counter[BB];   // zero-init; finisher resets to 0 each call

static __device__ __forceinline__ unsigned long long umin64(unsigned long long a,
                                                            unsigned long long b) {
    return a < b ? a : b;
}

// ---------------------------------------------------------------------------
// Fused kernel: cp.async.bulk row-staged ring; per stage the buffer is
// register-staged (8 LDS) and the refill is issued BEFORE the compute tail,
// so butterfly/score latency overlaps TMA delivery. 8-lane subgroup scoring,
// per-warp top-8, block merge, fused finisher.
// Keys: (score_bits << 32) | (j-1) -> min-order = (score asc, index asc),
// matching lax.top_k(-score) tie-break semantics.
// ---------------------------------------------------------------------------
__global__ __launch_bounds__(THREADS, 2)
void fused_kernel(const float* __restrict__ x,   // (B, N, FDIM)
                  const float* __restrict__ hf,  // (B, N, L, DH)
                  const float* __restrict__ he,  // (B, N, FDIM)
                  unsigned long long* __restrict__ cand,
                  float* __restrict__ out)
{
    const int b   = blockIdx.x / BLKS_PER_B;
    const int blk = blockIdx.x % BLKS_PER_B;
    const int t   = threadIdx.x;
    const int w   = t >> 5;        // warp 0..7
    const int l   = t & 31;        // lane
    const int sg  = l >> 3;        // subgroup 0..3 (row within warp's 4)
    const int sl  = l & 7;         // slice lane 0..7 (16 floats each)
    const int j0  = 1 + blk * ROWS_PER_BLK;

    extern __shared__ char dynsmem[];
    const uint32_t smem_u32 = (uint32_t)__cvta_generic_to_shared(dynsmem);

    __shared__ unsigned long long mbar[NBUF];
    __shared__ unsigned long long skeys[64];
    __shared__ int s_last;
    __shared__ int sel_idx[KK];
    const uint32_t mbar_u32 = (uint32_t)__cvta_generic_to_shared(mbar);

    if (t == 0) {
        #pragma unroll
        for (int s = 0; s < NBUF; s++)
            asm volatile("mbarrier.init.shared.b64 [%0], 1;"
                         :: "r"(mbar_u32 + s * 8) : "memory");
        asm volatile("fence.proxy.async.shared::cta;" ::: "memory");
    }
    __syncthreads();

    const float* xrow = x  + (size_t)b * NN * FDIM;
    const float* urow = he + (size_t)b * NN * FDIM;
    const float4* xb4 = (const float4*)xrow;
    const float4* ub4 = (const float4*)urow;

    // ---- bulk-issue stage cc into buffer cc%3 (single thread) ----
    auto issue = [&](int cc) {
        if (t == 0) {
            const int st   = cc % NBUF;
            const int row0 = j0 + cc * STAGE_ROWS;
            int nrows = NN - row0; if (nrows > STAGE_ROWS) nrows = STAGE_ROWS;
            const uint32_t bytes1 = (uint32_t)nrows * (FDIM * 4);
            const uint32_t mb = mbar_u32 + st * 8;
            asm volatile("mbarrier.arrive.expect_tx.shared.b64 _, [%0], %1;"
                         :: "r"(mb), "r"(2u * bytes1) : "memory");
            const uint32_t d0 = smem_u32 + (uint32_t)st * STAGE_B;
            asm volatile(
                "cp.async.bulk.shared::cta.global.mbarrier::complete_tx::bytes "
                "[%0], [%1], %2, [%3];"
                :: "r"(d0), "l"(xrow + (size_t)row0 * FDIM), "r"(bytes1), "r"(mb)
                : "memory");
            asm volatile(
                "cp.async.bulk.shared::cta.global.mbarrier::complete_tx::bytes "
                "[%0], [%1], %2, [%3];"
                :: "r"(d0 + STAGE_B1), "l"(urow + (size_t)row0 * FDIM), "r"(bytes1), "r"(mb)
                : "memory");
        }
    };

    auto waitbar = [&](int st, int phase) {
        const uint32_t mb = mbar_u32 + st * 8;
        asm volatile(
            "{\n\t.reg .pred P1;\n"
            "W_%=:\n\t"
            "mbarrier.try_wait.parity.acquire.cta.shared::cta.b64 P1, [%0], %1;\n\t"
            "@P1 bra.uni D_%=;\n\t"
            "bra.uni W_%=;\n"
            "D_%=:\n\t}"
            :: "r"(mb), "r"(phase) : "memory");
    };

    // ---- prefill the ring ----
    issue(0);
    issue(1);
    issue(2);

    // ---- centers in registers: this lane's 16-float slice (f4s q*8+sl) ----
    float4 C[4], V[4];
    #pragma unroll
    for (int q = 0; q < 4; q++) { C[q] = xb4[q * 8 + sl]; V[q] = ub4[q * 8 + sl]; }

    float vv = 0.0f;
    #pragma unroll
    for (int q = 0; q < 4; q++)
        vv += V[q].x*V[q].x + V[q].y*V[q].y + V[q].z*V[q].z + V[q].w*V[q].w;
    #pragma unroll
    for (int off = 1; off < 8; off <<= 1)
        vv += __shfl_xor_sync(FULL, vv, off);
    const float vnm = fmaxf(sqrtf(vv), 1e-8f);

    // ---- center direction (uniform) ----
    const float* h0 = hf + (size_t)b * NN * LDH;
    float2 p048 = *(const float2*)(h0 + 192);
    float2 p049 = *(const float2*)(h0 + 196);
    float d0x = p049.x - p048.x, d0y = p049.y - p048.y;
    float inv0 = 1.0f / fmaxf(sqrtf(d0x*d0x + d0y*d0y), 1e-12f);
    const float cdx = d0x * inv0 + 1e-8f;
    const float cdy = d0y * inv0 + 1e-8f;
    const float cnorm = fmaxf(sqrtf(cdx*cdx + cdy*cdy), 1e-8f);

    // ---- vsim precompute: lane l holds agents idx=l (lo) and idx=l+32 (hi)
    //      row(idx) = j0 + (idx>>2)*32 + w*4 + (idx&3) ----
    auto vsim_of = [&](int row) -> float {
        int r = row < NN ? row : NN - 1;
        const float* hj = hf + ((size_t)b * NN + r) * LDH;
        float2 a48 = *(const float2*)(hj + 192);
        float2 a49 = *(const float2*)(hj + 196);
        float djx = a49.x - a48.x, djy = a49.y - a48.y;
        float invj = 1.0f / fmaxf(sqrtf(djx*djx + djy*djy), 1e-12f);
        float odx = djx * invj + 1e-8f;
        float ody = djy * invj + 1e-8f;
        float vnum = odx*cdx + ody*cdy;
        float vden = fmaxf(sqrtf(odx*odx + ody*ody), 1e-8f) * cnorm;
        return vnum / vden;
    };
    const int row_lo = j0 + (l >> 2) * 32 + w * 4 + (l & 3);
    const float vs_lo = vsim_of(row_lo);
    const float vs_hi = vsim_of(row_lo + 256);

    // ---- main loop: 16 row-stages; refill issued BEFORE the compute tail ----
    unsigned long long k0 = KEY_MAX, k1 = KEY_MAX;

    #pragma unroll 2
    for (int cc = 0; cc < NSTAGE; cc++) {
        waitbar(cc % NBUF, (cc / NBUF) & 1);

        // register-stage this subgroup's row (the ONLY reads of this buffer)
        const float4* sx = (const float4*)(dynsmem + (cc % NBUF) * STAGE_B)
                           + (w * 4 + sg) * (FDIM / 4);
        const float4* su = (const float4*)(dynsmem + (cc % NBUF) * STAGE_B + STAGE_B1)
                           + (w * 4 + sg) * (FDIM / 4);
        float4 A0 = sx[sl],      U0 = su[sl];
        float4 A1 = sx[8 + sl],  U1 = su[8 + sl];
        float4 A2 = sx[16 + sl], U2 = su[16 + sl];
        float4 A3 = sx[24 + sl], U3 = su[24 + sl];

        // all warps finished READING buffer cc%3 -> refill immediately,
        // overlapping the whole compute tail with delivery
        __syncthreads();
        if (cc + 3 < NSTAGE) issue(cc + 3);

        float d2 = 0.0f, tn = 0.0f, uu = 0.0f;
        {
            float ex = A0.x-C[0].x, ey = A0.y-C[0].y, ez = A0.z-C[0].z, ew = A0.w-C[0].w;
            d2 += ex*ex + ey*ey + ez*ez + ew*ew;
            tn += U0.x*V[0].x + U0.y*V[0].y + U0.z*V[0].z + U0.w*V[0].w;
            uu += U0.x*U0.x + U0.y*U0.y + U0.z*U0.z + U0.w*U0.w;
        }
        {
            float ex = A1.x-C[1].x, ey = A1.y-C[1].y, ez = A1.z-C[1].z, ew = A1.w-C[1].w;
            d2 += ex*ex + ey*ey + ez*ez + ew*ew;
            tn += U1.x*V[1].x + U1.y*V[1].y + U1.z*V[1].z + U1.w*V[1].w;
            uu += U1.x*U1.x + U1.y*U1.y + U1.z*U1.z + U1.w*U1.w;
        }
        {
            float ex = A2.x-C[2].x, ey = A2.y-C[2].y, ez = A2.z-C[2].z, ew = A2.w-C[2].w;
            d2 += ex*ex + ey*ey + ez*ez + ew*ew;
            tn += U2.x*V[2].x + U2.y*V[2].y + U2.z*V[2].z + U2.w*V[2].w;
            uu += U2.x*U2.x + U2.y*U2.y + U2.z*U2.z + U2.w*U2.w;
        }
        {
            float ex = A3.x-C[3].x, ey = A3.y-C[3].y, ez = A3.z-C[3].z, ew = A3.w-C[3].w;
            d2 += ex*ex + ey*ey + ez*ez + ew*ew;
            tn += U3.x*V[3].x + U3.y*V[3].y + U3.z*V[3].z + U3.w*V[3].w;
            uu += U3.x*U3.x + U3.y*U3.y + U3.z*U3.z + U3.w*U3.w;
        }

        #pragma unroll
        for (int off = 1; off < 8; off <<= 1) {
            d2 += __shfl_xor_sync(FULL, d2, off);
            tn += __shfl_xor_sync(FULL, tn, off);
            uu += __shfl_xor_sync(FULL, uu, off);
        }

        // vsim for this subgroup's agent: lives on lane ((cc&7)*4 + sg)
        float vsrc = (cc < 8) ? vs_lo : vs_hi;
        float vs = __shfl_sync(FULL, vsrc, ((cc & 7) << 2) + sg);

        float tsim  = tn / (fmaxf(sqrtf(uu), 1e-8f) * vnm);
        float score = 0.3f * sqrtf(d2)
                    + 0.5f * (1.0f - fmaxf(vs,   0.0f))
                    + 0.4f * (1.0f - fmaxf(tsim, 0.0f));
        score = fmaxf(score, 0.0f);   // keep bit-pattern order-preserving

        // collector: lane with (l>>2)==(cc&7) stores subgroup (l&3)'s key
        float sc = __shfl_sync(FULL, score, (l & 3) << 3);
        const int jc = j0 + cc * 32 + w * 4 + (l & 3);
        if ((l >> 2) == (cc & 7) && jc < NN) {
            unsigned long long key =
                ((unsigned long long)__float_as_uint(sc) << 32)
                | (unsigned int)(jc - 1);
            if (cc < 8) k0 = key; else k1 = key;
        }
    }

    // ---- warp top-8 over 64 keys (2 per lane) ----
    unsigned long long sel = KEY_MAX;
    #pragma unroll
    for (int it = 0; it < KK; it++) {
        unsigned long long m = umin64(k0, k1);
        #pragma unroll
        for (int off = 16; off > 0; off >>= 1)
            m = umin64(m, __shfl_xor_sync(FULL, m, off));
        if (k0 == m) k0 = KEY_MAX;
        else if (k1 == m) k1 = KEY_MAX;
        if (l == it) sel = m;
    }
    if (l < KK) skeys[w * KK + l] = sel;
    __syncthreads();

    // ---- block merge: warp 0 reduces 64 -> 8, writes candidates ----
    if (w == 0) {
        unsigned long long a0 = skeys[l];
        unsigned long long a1 = skeys[l + 32];
        unsigned long long sel2 = KEY_MAX;
        #pragma unroll
        for (int it = 0; it < KK; it++) {
            unsigned long long m = umin64(a0, a1);
            #pragma unroll
            for (int off = 16; off > 0; off >>= 1)
                m = umin64(m, __shfl_xor_sync(FULL, m, off));
            if (a0 == m) a0 = KEY_MAX;
            else if (a1 == m) a1 = KEY_MAX;
            if (l == it) sel2 = m;
        }
        if (l < KK)
            cand[(size_t)b * CANDS + blk * KK + l] = sel2;
    }

    // ---- arrival protocol: last block of this batch merges + gathers ----
    __threadfence();
    __syncthreads();
    if (t == 0) {
        int old = atomicAdd(&g_counter[b], 1);
        s_last = (old == BLKS_PER_B - 1) ? 1 : 0;
    }
    __syncthreads();
    if (!s_last) return;

    __threadfence();   // acquire: see all other blocks' cand writes

    if (t < 32) {
        unsigned long long q0 = cand[(size_t)b * CANDS + t];
        unsigned long long q1 = cand[(size_t)b * CANDS + 32 + t];
        #pragma unroll
        for (int it = 0; it < KK; it++) {
            unsigned long long m = umin64(q0, q1);
            #pragma unroll
            for (int off = 16; off > 0; off >>= 1)
                m = umin64(m, __shfl_xor_sync(FULL, m, off));
            if (q0 == m) q0 = KEY_MAX;
            else if (q1 == m) q1 = KEY_MAX;
            if (t == 0) sel_idx[it] = (int)(unsigned int)(m & 0xFFFFFFFFu);
        }
        if (t == 0) g_counter[b] = 0;   // reset for next graph replay
    }
    __syncthreads();

    // gather: 256 threads = 8 rows x 32 lanes of float4
    {
        const int kk  = t >> 5;
        const int idx = sel_idx[kk];
        float4 val = xb4[(size_t)(idx + 1) * 32 + l];
        ((float4*)(out + ((size_t)b * KK + kk) * FDIM))[l] = val;
    }
    if (t < KK)
        out[(size_t)BB * KK * FDIM + b * KK + t] = (float)sel_idx[t];
}

extern "C" void kernel_launch(void* const* d_in, const int* in_sizes, int n_in,
                              void* d_out, int out_size)
{
    const float* x  = (const float*)d_in[0];   // (B, N, FDIM) f32
    const float* hf = (const float*)d_in[1];   // (B, N, L, DH) f32
    const float* he = (const float*)d_in[2];   // (B, N, FDIM) f32
    float* out = (float*)d_out;

    unsigned long long* cand;
    cudaGetSymbolAddress((void**)&cand, g_cand);

    cudaFuncSetAttribute(fused_kernel,
                         cudaFuncAttributeMaxDynamicSharedMemorySize, SMEM_BYTES);

    fused_kernel<<<BB * BLKS_PER_B, THREADS, SMEM_BYTES>>>(x, hf, he, cand, out);
}